// round 1
// baseline (speedup 1.0000x reference)
#include <cuda_runtime.h>
#include <math_constants.h>

// PhiCell hysteresis scan:
//   out_i = Phi(x_i - out_{i-1}) + out_{i-1},  x_i = in_i * k
// is exactly out_i = clamp(out_{i-1}, x_i, x_i + 1).
// Clamp-map composition is associative -> parallel prefix scan over (L,H).

#define BLOCK 256
#define ITEMS 16
#define CHUNK (BLOCK * ITEMS)   // 4096 elements per block
#define MAXB  4096              // max number of phase-1 blocks supported

struct CH { float L, H; };

__device__ __forceinline__ CH ch_id() {
    CH r; r.L = -CUDART_INF_F; r.H = CUDART_INF_F; return r;
}

// compose: apply a FIRST, then b.
__device__ __forceinline__ CH ch_comp(CH a, CH b) {
    CH r;
    r.L = fminf(fmaxf(a.L, b.L), b.H);
    r.H = fminf(fmaxf(a.H, b.L), b.H);
    return r;
}

// scratch (no cudaMalloc allowed)
__device__ float2 g_part[MAXB];
__device__ float2 g_excl[MAXB];

__device__ __forceinline__ CH warp_incl_scan(CH v, int lane) {
#pragma unroll
    for (int off = 1; off < 32; off <<= 1) {
        float pl = __shfl_up_sync(0xffffffffu, v.L, off);
        float ph = __shfl_up_sync(0xffffffffu, v.H, off);
        if (lane >= off) { CH p; p.L = pl; p.H = ph; v = ch_comp(p, v); }
    }
    return v;
}

// Returns composite of all threads with smaller threadIdx (identity for t==0).
// Must be called by all threads of the block.
__device__ CH block_excl_scan(CH v) {
    __shared__ CH ws[BLOCK / 32];
    int lane = threadIdx.x & 31;
    int wid  = threadIdx.x >> 5;

    CH vi = warp_incl_scan(v, lane);
    if (lane == 31) ws[wid] = vi;
    __syncthreads();
    if (wid == 0) {
        CH w = (lane < BLOCK / 32) ? ws[lane] : ch_id();
        w = warp_incl_scan(w, lane);
        if (lane < BLOCK / 32) ws[lane] = w;
    }
    __syncthreads();
    CH wp = (wid > 0) ? ws[wid - 1] : ch_id();

    float pl = __shfl_up_sync(0xffffffffu, vi.L, 1);
    float ph = __shfl_up_sync(0xffffffffu, vi.H, 1);
    CH ve = ch_id();
    if (lane > 0) { ve.L = pl; ve.H = ph; }
    return ch_comp(wp, ve);
}

__device__ __forceinline__ void ch_absorb(CH& c, float x) {
    float hx = x + 1.0f;
    c.L = fminf(fmaxf(c.L, x), hx);
    c.H = fminf(fmaxf(c.H, x), hx);
}

// Phase 1: per-block composite
__global__ void __launch_bounds__(BLOCK)
k_phase1(const float* __restrict__ in, const float* __restrict__ kw) {
    float k = __ldg(kw);
    int base = blockIdx.x * CHUNK + threadIdx.x * ITEMS;
    const float4* p = reinterpret_cast<const float4*>(in + base);
    CH c = ch_id();
#pragma unroll
    for (int q = 0; q < ITEMS / 4; q++) {
        float4 x4 = __ldg(&p[q]);
        ch_absorb(c, x4.x * k);
        ch_absorb(c, x4.y * k);
        ch_absorb(c, x4.z * k);
        ch_absorb(c, x4.w * k);
    }
    CH e = block_excl_scan(c);
    if (threadIdx.x == BLOCK - 1) {
        CH t = ch_comp(e, c);                 // block total
        g_part[blockIdx.x] = make_float2(t.L, t.H);
    }
}

// Phase 2: exclusive scan of block composites (single block)
__global__ void __launch_bounds__(BLOCK)
k_phase2(int nb) {
    int t = threadIdx.x;
    const int P = MAXB / BLOCK;               // 16
    CH loc[P];
    CH c = ch_id();
#pragma unroll
    for (int j = 0; j < P; j++) {
        int i = t * P + j;
        CH x = ch_id();
        if (i < nb) { float2 f = g_part[i]; x.L = f.x; x.H = f.y; }
        c = ch_comp(c, x);
        loc[j] = c;                           // local inclusive
    }
    CH te = block_excl_scan(c);
#pragma unroll
    for (int j = 0; j < P; j++) {
        int i = t * P + j;
        if (i < nb) {
            CH e = (j == 0) ? te : ch_comp(te, loc[j - 1]);
            g_excl[i] = make_float2(e.L, e.H);
        }
    }
}

// Phase 3: apply prefixes and emit outputs
__global__ void __launch_bounds__(BLOCK)
k_phase3(const float* __restrict__ in, const float* __restrict__ kw,
         const float* __restrict__ st, float* __restrict__ out,
         int n, int out_size) {
    float k  = __ldg(kw);
    float s0 = __ldg(st);
    int base = blockIdx.x * CHUNK + threadIdx.x * ITEMS;
    const float4* p = reinterpret_cast<const float4*>(in + base);

    float x[ITEMS];
#pragma unroll
    for (int q = 0; q < ITEMS / 4; q++) {
        float4 x4 = __ldg(&p[q]);
        x[4 * q + 0] = x4.x * k;
        x[4 * q + 1] = x4.y * k;
        x[4 * q + 2] = x4.z * k;
        x[4 * q + 3] = x4.w * k;
    }

    CH c = ch_id();
#pragma unroll
    for (int j = 0; j < ITEMS; j++) ch_absorb(c, x[j]);

    CH te = block_excl_scan(c);
    float2 be2 = g_excl[blockIdx.x];
    CH be; be.L = be2.x; be.H = be2.y;
    CH run = ch_comp(be, te);                 // composite of everything before my items

    float4* o = reinterpret_cast<float4*>(out + base);
#pragma unroll
    for (int q = 0; q < ITEMS / 4; q++) {
        float4 r;
        ch_absorb(run, x[4 * q + 0]); r.x = fminf(fmaxf(s0, run.L), run.H);
        ch_absorb(run, x[4 * q + 1]); r.y = fminf(fmaxf(s0, run.L), run.H);
        ch_absorb(run, x[4 * q + 2]); r.z = fminf(fmaxf(s0, run.L), run.H);
        ch_absorb(run, x[4 * q + 3]); r.w = fminf(fmaxf(s0, run.L), run.H);
        o[q] = r;
    }

    // new_state = last output value (appended after the T outputs, if present)
    if (base + ITEMS == n && out_size > n) {
        out[n] = fminf(fmaxf(s0, run.L), run.H);
    }
}

extern "C" void kernel_launch(void* const* d_in, const int* in_sizes, int n_in,
                              void* d_out, int out_size) {
    const float* in = (const float*)d_in[0];   // inputs [1, T]
    const float* st = (const float*)d_in[1];   // state  [1, 1]
    const float* kw = (const float*)d_in[2];   // kernel [1, 1]
    float* out = (float*)d_out;

    int n  = in_sizes[0];
    int nb = n / CHUNK;                        // T = 2^23 -> 2048 blocks

    k_phase1<<<nb, BLOCK>>>(in, kw);
    k_phase2<<<1, BLOCK>>>(nb);
    k_phase3<<<nb, BLOCK>>>(in, kw, st, out, n, out_size);
}